// round 6
// baseline (speedup 1.0000x reference)
#include <cuda_runtime.h>
#include <cuda_bf16.h>

// DotPredictor: out[e] = sigmoid(dot(h[src[e]], h[dst[e]])), D = 64 fp32.
// Indices are int32 (JAX x64 disabled).
// 8 lanes per group, 4 edges per group: 16 front-batched LDG.128 per thread
// (true MLP ~16, enabled by launch_bounds reg budget), each warp-level LDG
// covers full 128B lines. h (12.8 MB) is L2-resident; target: L2 roofline.

#define D 64

__global__ void __launch_bounds__(256, 3) dotpred_kernel(
    const float* __restrict__ h,
    const int* __restrict__ src,
    const int* __restrict__ dst,
    float* __restrict__ out,
    int E)
{
    int gid   = blockIdx.x * blockDim.x + threadIdx.x;
    int group = gid >> 3;            // 8 lanes per group
    int lane  = gid & 7;
    int e0 = group * 4;
    if (e0 >= E) return;

    // Vectorized index loads: 4 edges, 16B-aligned
    int4 ss = reinterpret_cast<const int4*>(src)[group];
    int4 dd = reinterpret_cast<const int4*>(dst)[group];

    // Clamp tail edges onto edge 0's indices (stores are guarded below)
    int s0 = ss.x, d0 = dd.x;
    int s1 = (e0 + 1 < E) ? ss.y : ss.x;
    int d1 = (e0 + 1 < E) ? dd.y : dd.x;
    int s2 = (e0 + 2 < E) ? ss.z : ss.x;
    int d2 = (e0 + 2 < E) ? dd.z : dd.x;
    int s3 = (e0 + 3 < E) ? ss.w : ss.x;
    int d3 = (e0 + 3 < E) ? dd.w : dd.x;

    const float4* __restrict__ s0p = reinterpret_cast<const float4*>(h + (long long)s0 * D);
    const float4* __restrict__ d0p = reinterpret_cast<const float4*>(h + (long long)d0 * D);
    const float4* __restrict__ s1p = reinterpret_cast<const float4*>(h + (long long)s1 * D);
    const float4* __restrict__ d1p = reinterpret_cast<const float4*>(h + (long long)d1 * D);
    const float4* __restrict__ s2p = reinterpret_cast<const float4*>(h + (long long)s2 * D);
    const float4* __restrict__ d2p = reinterpret_cast<const float4*>(h + (long long)d2 * D);
    const float4* __restrict__ s3p = reinterpret_cast<const float4*>(h + (long long)s3 * D);
    const float4* __restrict__ d3p = reinterpret_cast<const float4*>(h + (long long)d3 * D);

    // 16 independent LDG.128 — front-batched for maximum MLP
    float4 a0 = s0p[lane];
    float4 a1 = s0p[lane + 8];
    float4 b0 = d0p[lane];
    float4 b1 = d0p[lane + 8];
    float4 c0 = s1p[lane];
    float4 c1 = s1p[lane + 8];
    float4 f0 = d1p[lane];
    float4 f1 = d1p[lane + 8];
    float4 g0 = s2p[lane];
    float4 g1 = s2p[lane + 8];
    float4 k0 = d2p[lane];
    float4 k1 = d2p[lane + 8];
    float4 m0 = s3p[lane];
    float4 m1 = s3p[lane + 8];
    float4 n0 = d3p[lane];
    float4 n1 = d3p[lane + 8];

    float acc0 = a0.x * b0.x;
    float acc1 = c0.x * f0.x;
    float acc2 = g0.x * k0.x;
    float acc3 = m0.x * n0.x;
    acc0 = fmaf(a0.y, b0.y, acc0);
    acc1 = fmaf(c0.y, f0.y, acc1);
    acc2 = fmaf(g0.y, k0.y, acc2);
    acc3 = fmaf(m0.y, n0.y, acc3);
    acc0 = fmaf(a0.z, b0.z, acc0);
    acc1 = fmaf(c0.z, f0.z, acc1);
    acc2 = fmaf(g0.z, k0.z, acc2);
    acc3 = fmaf(m0.z, n0.z, acc3);
    acc0 = fmaf(a0.w, b0.w, acc0);
    acc1 = fmaf(c0.w, f0.w, acc1);
    acc2 = fmaf(g0.w, k0.w, acc2);
    acc3 = fmaf(m0.w, n0.w, acc3);
    acc0 = fmaf(a1.x, b1.x, acc0);
    acc1 = fmaf(c1.x, f1.x, acc1);
    acc2 = fmaf(g1.x, k1.x, acc2);
    acc3 = fmaf(m1.x, n1.x, acc3);
    acc0 = fmaf(a1.y, b1.y, acc0);
    acc1 = fmaf(c1.y, f1.y, acc1);
    acc2 = fmaf(g1.y, k1.y, acc2);
    acc3 = fmaf(m1.y, n1.y, acc3);
    acc0 = fmaf(a1.z, b1.z, acc0);
    acc1 = fmaf(c1.z, f1.z, acc1);
    acc2 = fmaf(g1.z, k1.z, acc2);
    acc3 = fmaf(m1.z, n1.z, acc3);
    acc0 = fmaf(a1.w, b1.w, acc0);
    acc1 = fmaf(c1.w, f1.w, acc1);
    acc2 = fmaf(g1.w, k1.w, acc2);
    acc3 = fmaf(m1.w, n1.w, acc3);

    // Reduce all four accumulators across the 8-lane group
    acc0 += __shfl_xor_sync(0xFFFFFFFFu, acc0, 4);
    acc1 += __shfl_xor_sync(0xFFFFFFFFu, acc1, 4);
    acc2 += __shfl_xor_sync(0xFFFFFFFFu, acc2, 4);
    acc3 += __shfl_xor_sync(0xFFFFFFFFu, acc3, 4);
    acc0 += __shfl_xor_sync(0xFFFFFFFFu, acc0, 2);
    acc1 += __shfl_xor_sync(0xFFFFFFFFu, acc1, 2);
    acc2 += __shfl_xor_sync(0xFFFFFFFFu, acc2, 2);
    acc3 += __shfl_xor_sync(0xFFFFFFFFu, acc3, 2);
    acc0 += __shfl_xor_sync(0xFFFFFFFFu, acc0, 1);
    acc1 += __shfl_xor_sync(0xFFFFFFFFu, acc1, 1);
    acc2 += __shfl_xor_sync(0xFFFFFFFFu, acc2, 1);
    acc3 += __shfl_xor_sync(0xFFFFFFFFu, acc3, 1);

    if (lane == 0) {
        out[e0] = 1.0f / (1.0f + __expf(-acc0));
        if (e0 + 1 < E) out[e0 + 1] = 1.0f / (1.0f + __expf(-acc1));
        if (e0 + 2 < E) out[e0 + 2] = 1.0f / (1.0f + __expf(-acc2));
        if (e0 + 3 < E) out[e0 + 3] = 1.0f / (1.0f + __expf(-acc3));
    }
}

extern "C" void kernel_launch(void* const* d_in, const int* in_sizes, int n_in,
                              void* d_out, int out_size)
{
    const float* h   = (const float*)d_in[0];
    const int*   src = (const int*)d_in[1];
    const int*   dst = (const int*)d_in[2];
    float*       out = (float*)d_out;

    int E = in_sizes[1];  // number of edges

    long long groups = ((long long)E + 3) / 4;
    long long total_threads = groups * 8;
    int threads = 256;
    int blocks  = (int)((total_threads + threads - 1) / threads);

    dotpred_kernel<<<blocks, threads>>>(h, src, dst, out, E);
}

// round 7
// speedup vs baseline: 1.1737x; 1.1737x over previous
#include <cuda_runtime.h>
#include <cuda_bf16.h>

// DotPredictor: out[e] = sigmoid(dot(h[src[e]], h[dst[e]])), D = 64 fp32.
// Indices are int32 (JAX x64 disabled).
// 8 lanes per group, 2 edges per group; 8 LDG.128/thread, each warp-level
// LDG covers full 128B lines (wavefront-optimal). Merged 5-shuffle reduction
// for both edges; single float2 store. h (12.8 MB) is L2-resident.

#define D 64

__global__ void __launch_bounds__(256, 6) dotpred_kernel(
    const float* __restrict__ h,
    const int* __restrict__ src,
    const int* __restrict__ dst,
    float* __restrict__ out,
    int E)
{
    int gid   = blockIdx.x * blockDim.x + threadIdx.x;
    int group = gid >> 3;            // 8 lanes per group
    int lane  = gid & 7;
    int e0 = group * 2;
    if (e0 >= E) return;
    bool has_e1 = (e0 + 1 < E);

    // Vectorized index loads: edge pair is 8B-aligned in src/dst
    int2 ss = reinterpret_cast<const int2*>(src)[group];
    int2 dd = reinterpret_cast<const int2*>(dst)[group];

    const float4* __restrict__ s0p =
        reinterpret_cast<const float4*>(h + (long long)ss.x * D);
    const float4* __restrict__ d0p =
        reinterpret_cast<const float4*>(h + (long long)dd.x * D);
    const float4* __restrict__ s1p =
        reinterpret_cast<const float4*>(h + (long long)(has_e1 ? ss.y : ss.x) * D);
    const float4* __restrict__ d1p =
        reinterpret_cast<const float4*>(h + (long long)(has_e1 ? dd.y : dd.x) * D);

    // 8 independent 16B loads; each warp-level LDG covers 4 full 128B lines
    float4 a0 = s0p[lane];
    float4 a1 = s0p[lane + 8];
    float4 b0 = d0p[lane];
    float4 b1 = d0p[lane + 8];
    float4 c0 = s1p[lane];
    float4 c1 = s1p[lane + 8];
    float4 f0 = d1p[lane];
    float4 f1 = d1p[lane + 8];

    float acc0 = a0.x * b0.x;
    float acc1 = c0.x * f0.x;
    acc0 = fmaf(a0.y, b0.y, acc0);
    acc1 = fmaf(c0.y, f0.y, acc1);
    acc0 = fmaf(a0.z, b0.z, acc0);
    acc1 = fmaf(c0.z, f0.z, acc1);
    acc0 = fmaf(a0.w, b0.w, acc0);
    acc1 = fmaf(c0.w, f0.w, acc1);
    acc0 = fmaf(a1.x, b1.x, acc0);
    acc1 = fmaf(c1.x, f1.x, acc1);
    acc0 = fmaf(a1.y, b1.y, acc0);
    acc1 = fmaf(c1.y, f1.y, acc1);
    acc0 = fmaf(a1.z, b1.z, acc0);
    acc1 = fmaf(c1.z, f1.z, acc1);
    acc0 = fmaf(a1.w, b1.w, acc0);
    acc1 = fmaf(c1.w, f1.w, acc1);

    // Merged reduction: fold edge-1 tree into lanes 4-7, then one shared tree.
    float t0 = __shfl_xor_sync(0xFFFFFFFFu, acc0, 4);
    float t1 = __shfl_xor_sync(0xFFFFFFFFu, acc1, 4);
    float v  = (lane < 4) ? (acc0 + t0) : (acc1 + t1);
    v += __shfl_xor_sync(0xFFFFFFFFu, v, 2);
    v += __shfl_xor_sync(0xFFFFFFFFu, v, 1);
    // lane 0 holds sum(acc0); lane 4 holds sum(acc1); pull acc1 to lane 0
    float w = __shfl_xor_sync(0xFFFFFFFFu, v, 4);

    if (lane == 0) {
        float r0 = 1.0f / (1.0f + __expf(-v));
        if (has_e1) {
            float r1 = 1.0f / (1.0f + __expf(-w));
            reinterpret_cast<float2*>(out)[group] = make_float2(r0, r1);
        } else {
            out[e0] = r0;
        }
    }
}

extern "C" void kernel_launch(void* const* d_in, const int* in_sizes, int n_in,
                              void* d_out, int out_size)
{
    const float* h   = (const float*)d_in[0];
    const int*   src = (const int*)d_in[1];
    const int*   dst = (const int*)d_in[2];
    float*       out = (float*)d_out;

    int E = in_sizes[1];  // number of edges

    long long groups = ((long long)E + 1) / 2;
    long long total_threads = groups * 8;
    int threads = 256;
    int blocks  = (int)((total_threads + threads - 1) / threads);

    dotpred_kernel<<<blocks, threads>>>(h, src, dst, out, E);
}

// round 8
// speedup vs baseline: 1.1752x; 1.0013x over previous
#include <cuda_runtime.h>
#include <cuda_bf16.h>

// DotPredictor: out[e] = sigmoid(dot(h[src[e]], h[dst[e]])), D = 64 fp32.
// Indices are int32 (JAX x64 disabled).
// 8 lanes per group, 2 edges per group; 8 LDG.128/thread, each warp-level
// LDG covers full 128B lines (wavefront-optimal). 4-shuffle merged reduction;
// lane 0 stores edge0, lane 4 stores edge1 (parallel sigmoid).
// No reg cap: occupancy-first (32 regs, ~86% occ). h is L2-resident.

#define D 64

__global__ void __launch_bounds__(256) dotpred_kernel(
    const float* __restrict__ h,
    const int* __restrict__ src,
    const int* __restrict__ dst,
    float* __restrict__ out,
    int E)
{
    int gid   = blockIdx.x * blockDim.x + threadIdx.x;
    int group = gid >> 3;            // 8 lanes per group
    int lane  = gid & 7;
    int e0 = group * 2;
    if (e0 >= E) return;
    bool has_e1 = (e0 + 1 < E);

    // Vectorized index loads: edge pair is 8B-aligned in src/dst
    int2 ss = reinterpret_cast<const int2*>(src)[group];
    int2 dd = reinterpret_cast<const int2*>(dst)[group];

    const float4* __restrict__ s0p =
        reinterpret_cast<const float4*>(h + (long long)ss.x * D);
    const float4* __restrict__ d0p =
        reinterpret_cast<const float4*>(h + (long long)dd.x * D);
    const float4* __restrict__ s1p =
        reinterpret_cast<const float4*>(h + (long long)(has_e1 ? ss.y : ss.x) * D);
    const float4* __restrict__ d1p =
        reinterpret_cast<const float4*>(h + (long long)(has_e1 ? dd.y : dd.x) * D);

    // 8 independent 16B loads; each warp-level LDG covers 4 full 128B lines
    float4 a0 = s0p[lane];
    float4 a1 = s0p[lane + 8];
    float4 b0 = d0p[lane];
    float4 b1 = d0p[lane + 8];
    float4 c0 = s1p[lane];
    float4 c1 = s1p[lane + 8];
    float4 f0 = d1p[lane];
    float4 f1 = d1p[lane + 8];

    float acc0 = a0.x * b0.x;
    float acc1 = c0.x * f0.x;
    acc0 = fmaf(a0.y, b0.y, acc0);
    acc1 = fmaf(c0.y, f0.y, acc1);
    acc0 = fmaf(a0.z, b0.z, acc0);
    acc1 = fmaf(c0.z, f0.z, acc1);
    acc0 = fmaf(a0.w, b0.w, acc0);
    acc1 = fmaf(c0.w, f0.w, acc1);
    acc0 = fmaf(a1.x, b1.x, acc0);
    acc1 = fmaf(c1.x, f1.x, acc1);
    acc0 = fmaf(a1.y, b1.y, acc0);
    acc1 = fmaf(c1.y, f1.y, acc1);
    acc0 = fmaf(a1.z, b1.z, acc0);
    acc1 = fmaf(c1.z, f1.z, acc1);
    acc0 = fmaf(a1.w, b1.w, acc0);
    acc1 = fmaf(c1.w, f1.w, acc1);

    // Merged reduction: edge0 result lands in lanes 0-3, edge1 in lanes 4-7.
    float t0 = __shfl_xor_sync(0xFFFFFFFFu, acc0, 4);
    float t1 = __shfl_xor_sync(0xFFFFFFFFu, acc1, 4);
    float v  = (lane < 4) ? (acc0 + t0) : (acc1 + t1);
    v += __shfl_xor_sync(0xFFFFFFFFu, v, 2);
    v += __shfl_xor_sync(0xFFFFFFFFu, v, 1);
    // lane 0 holds sum(edge0); lane 4 holds sum(edge1)

    if (lane == 0 || (lane == 4 && has_e1)) {
        out[e0 + (lane >> 2)] = 1.0f / (1.0f + __expf(-v));
    }
}

extern "C" void kernel_launch(void* const* d_in, const int* in_sizes, int n_in,
                              void* d_out, int out_size)
{
    const float* h   = (const float*)d_in[0];
    const int*   src = (const int*)d_in[1];
    const int*   dst = (const int*)d_in[2];
    float*       out = (float*)d_out;

    int E = in_sizes[1];  // number of edges

    long long groups = ((long long)E + 1) / 2;
    long long total_threads = groups * 8;
    int threads = 256;
    int blocks  = (int)((total_threads + threads - 1) / threads);

    dotpred_kernel<<<blocks, threads>>>(h, src, dst, out, E);
}